// round 14
// baseline (speedup 1.0000x reference)
#include <cuda_runtime.h>
#include <cuda_bf16.h>
#include <cuda_fp16.h>
#include <math.h>

typedef unsigned int u32;
typedef unsigned long long u64;

#define Bdim 4
#define Sdim 1024
#define Ddim 512
#define Fdim 2048
#define Hdim 8
#define Edim 8
#define HD 64
#define NTOK 4096
#define CAPMAX 256
#define QKVW 1536

// ---------------- scratch ----------------
__device__ float g_qkv [NTOK * QKVW];
__device__ float g_aout[NTOK * Ddim];
__device__ float g_h   [NTOK * Ddim];
__device__ float g_moe [NTOK * Ddim];
__device__ __nv_bfloat16 g_xh [NTOK * Ddim], g_xl [NTOK * Ddim];
__device__ __nv_bfloat16 g_iwh[QKVW * Ddim], g_iwl[QKVW * Ddim];
__device__ __nv_bfloat16 g_owh[Ddim * Ddim], g_owl[Ddim * Ddim];
__device__ __nv_bfloat16 g_qh [NTOK * Ddim], g_ql [NTOK * Ddim];
__device__ __nv_bfloat16 g_kh [NTOK * Ddim], g_kl [NTOK * Ddim];
__device__ __nv_bfloat16 g_vth[Bdim * Ddim * Sdim], g_vtl[Bdim * Ddim * Sdim];
__device__ __nv_bfloat16 g_ah [NTOK * Ddim], g_al [NTOK * Ddim];
__device__ half g_hgf[32 * CAPMAX * Ddim];
__device__ half g_ygf[32 * CAPMAX * Fdim];
__device__ half g_w1f[Edim * Fdim * Ddim];
__device__ half g_w2f[Edim * Ddim * Fdim];
__device__ int   g_idx [NTOK];
__device__ float g_pmax[NTOK];
__device__ int   g_etok[32 * CAPMAX];
__device__ float g_escale[32 * CAPMAX];
__device__ int   g_count[32];

// ---------------- helpers ----------------
__device__ __forceinline__ u32 smem_u32(const void* p) {
    u32 a;
    asm("{ .reg .u64 t; cvta.to.shared.u64 t, %1; cvt.u32.u64 %0, t; }" : "=r"(a) : "l"(p));
    return a;
}
__device__ __forceinline__ u32 bfpack(__nv_bfloat16 a, __nv_bfloat16 b) {
    __nv_bfloat162 t; t.x = a; t.y = b; return *(u32*)&t;
}
__device__ __forceinline__ void ldm4(u32 r[4], u32 addr) {
    asm volatile("ldmatrix.sync.aligned.m8n8.x4.shared.b16 {%0,%1,%2,%3}, [%4];"
                 : "=r"(r[0]), "=r"(r[1]), "=r"(r[2]), "=r"(r[3]) : "r"(addr));
}
__device__ __forceinline__ void mma16816(float c[4], const u32 a[4], const u32 b[2]) {
    asm volatile(
        "mma.sync.aligned.m16n8k16.row.col.f32.bf16.bf16.f32 "
        "{%0,%1,%2,%3}, {%4,%5,%6,%7}, {%8,%9}, {%0,%1,%2,%3};"
        : "+f"(c[0]), "+f"(c[1]), "+f"(c[2]), "+f"(c[3])
        : "r"(a[0]), "r"(a[1]), "r"(a[2]), "r"(a[3]), "r"(b[0]), "r"(b[1]));
}
__device__ __forceinline__ void mma16816h(float c[4], const u32 a[4], const u32 b[2]) {
    asm volatile(
        "mma.sync.aligned.m16n8k16.row.col.f32.f16.f16.f32 "
        "{%0,%1,%2,%3}, {%4,%5,%6,%7}, {%8,%9}, {%0,%1,%2,%3};"
        : "+f"(c[0]), "+f"(c[1]), "+f"(c[2]), "+f"(c[3])
        : "r"(a[0]), "r"(a[1]), "r"(a[2]), "r"(a[3]), "r"(b[0]), "r"(b[1]));
}
__device__ __forceinline__ void cp16(u32 dst, const void* src) {
    asm volatile("cp.async.cg.shared.global [%0], [%1], 16;" :: "r"(dst), "l"(src));
}
#define CP_COMMIT() asm volatile("cp.async.commit_group;" ::: "memory")
#define CP_WAIT1()  asm volatile("cp.async.wait_group 1;" ::: "memory")
#define CP_WAIT0()  asm volatile("cp.async.wait_group 0;" ::: "memory")
__device__ __forceinline__ float gelu_exact(float x) {
    return 0.5f * x * (1.0f + erff(x * 0.70710678118654752f));
}
__device__ __forceinline__ void split2(float v, __nv_bfloat16& h, __nv_bfloat16& l) {
    h = __float2bfloat16(v);
    l = __float2bfloat16(v - __bfloat162float(h));
}
__device__ __forceinline__ float fexp(float x) {
    float y = fmaxf(x * 1.4426950408889634f, -126.0f);
    int i = __float2int_rn(y);
    float f = y - (float)i;
    float p = 0.0013333558146f;
    p = fmaf(p, f, 0.0096181291076f);
    p = fmaf(p, f, 0.0555041086648f);
    p = fmaf(p, f, 0.2402265069591f);
    p = fmaf(p, f, 0.6931471805599f);
    p = fmaf(p, f, 1.0f);
    return __int_as_float(__float_as_int(p) + (i << 23));
}

// ========== pipelined HMMA bf16-split NT mainloop (128x128, 256 thr) ==========
#define GSTG 40960
#define GEMM_SMEM (2 * GSTG)

__device__ __forceinline__ void gemm_issue(
    u32 st, const __nv_bfloat16* Ah, const __nv_bfloat16* Al,
    const __nv_bfloat16* Bh, const __nv_bfloat16* Bl,
    int ldA, int ldB, int k0, int tid)
{
    int idx = tid;
#pragma unroll
    for (int t = 0; t < 8; t++, idx += 256) {
        int sel = idx >> 9;
        int q = idx & 511;
        int r = q >> 2, kq = q & 3;
        const __nv_bfloat16* src = (sel == 0 ? Ah : sel == 1 ? Al : sel == 2 ? Bh : Bl);
        int ld = (sel < 2) ? ldA : ldB;
        cp16(st + sel * 10240 + r * 80 + kq * 16, src + (size_t)r * ld + k0 + kq * 8);
    }
}

template<int K>
__device__ __forceinline__ void hmma_loop(
    const __nv_bfloat16* Ah, const __nv_bfloat16* Al,
    const __nv_bfloat16* Bh, const __nv_bfloat16* Bl,
    int ldA, int ldB, char* smbase, float (&c)[2][8][4])
{
    const int tid = threadIdx.x, lane = tid & 31, wid = tid >> 5;
    const int wm = (wid & 3) * 32, wn = (wid >> 2) * 64;
    const int rowA = (lane & 7) + ((lane >> 3) & 1) * 8;
    const int colA = (lane >> 4) * 16;
    const int rowB = (lane & 7) + (lane >> 4) * 8;
    const int colB = ((lane >> 3) & 1) * 16;
    const u32 sb = smem_u32(smbase);
    constexpr int NC = K / 32;

#pragma unroll
    for (int i = 0; i < 2; i++)
#pragma unroll
        for (int j = 0; j < 8; j++)
#pragma unroll
            for (int q = 0; q < 4; q++) c[i][j][q] = 0.0f;

    gemm_issue(sb, Ah, Al, Bh, Bl, ldA, ldB, 0, tid);
    CP_COMMIT();
    for (int ch = 0; ch < NC; ch++) {
        if (ch + 1 < NC) {
            gemm_issue(sb + ((ch + 1) & 1) * GSTG, Ah, Al, Bh, Bl, ldA, ldB, (ch + 1) * 32, tid);
            CP_COMMIT();
            CP_WAIT1();
        } else {
            CP_WAIT0();
        }
        __syncthreads();
        const u32 st = sb + (ch & 1) * GSTG;
#pragma unroll
        for (int kk = 0; kk < 32; kk += 16) {
            u32 ah[2][4], al[2][4], bh[8][2], bl[8][2];
#pragma unroll
            for (int s = 0; s < 2; s++) {
                ldm4(ah[s], st + (wm + s * 16 + rowA) * 80 + kk * 2 + colA);
                ldm4(al[s], st + 10240 + (wm + s * 16 + rowA) * 80 + kk * 2 + colA);
            }
#pragma unroll
            for (int p = 0; p < 4; p++) {
                u32 t4[4];
                ldm4(t4, st + 20480 + (wn + p * 16 + rowB) * 80 + kk * 2 + colB);
                bh[2 * p][0] = t4[0]; bh[2 * p][1] = t4[1];
                bh[2 * p + 1][0] = t4[2]; bh[2 * p + 1][1] = t4[3];
                ldm4(t4, st + 30720 + (wn + p * 16 + rowB) * 80 + kk * 2 + colB);
                bl[2 * p][0] = t4[0]; bl[2 * p][1] = t4[1];
                bl[2 * p + 1][0] = t4[2]; bl[2 * p + 1][1] = t4[3];
            }
#pragma unroll
            for (int i = 0; i < 2; i++)
#pragma unroll
                for (int j = 0; j < 8; j++) {
                    mma16816(c[i][j], ah[i], bh[j]);
                    mma16816(c[i][j], ah[i], bl[j]);
                    mma16816(c[i][j], al[i], bh[j]);
                }
        }
        __syncthreads();
    }
}

// ========== pipelined fp16 single-pass NT mainloop (128x128, 256 thr) ==========
#define HSTG 20480
#define HGEMM_SMEM (2 * HSTG)

__device__ __forceinline__ void hgemm_issue(
    u32 st, const half* A, const half* B, int ldA, int ldB, int k0, int tid)
{
    int idx = tid;
#pragma unroll
    for (int t = 0; t < 4; t++, idx += 256) {
        int sel = idx >> 9;
        int q = idx & 511;
        int r = q >> 2, kq = q & 3;
        const half* src = sel ? B : A;
        int ld = sel ? ldB : ldA;
        cp16(st + sel * 10240 + r * 80 + kq * 16, src + (size_t)r * ld + k0 + kq * 8);
    }
}

template<int K>
__device__ __forceinline__ void hgemm_loop(
    const half* A, const half* B, int ldA, int ldB, char* smbase, float (&c)[2][8][4])
{
    const int tid = threadIdx.x, lane = tid & 31, wid = tid >> 5;
    const int wm = (wid & 3) * 32, wn = (wid >> 2) * 64;
    const int rowA = (lane & 7) + ((lane >> 3) & 1) * 8;
    const int colA = (lane >> 4) * 16;
    const int rowB = (lane & 7) + (lane >> 4) * 8;
    const int colB = ((lane >> 3) & 1) * 16;
    const u32 sb = smem_u32(smbase);
    constexpr int NC = K / 32;

#pragma unroll
    for (int i = 0; i < 2; i++)
#pragma unroll
        for (int j = 0; j < 8; j++)
#pragma unroll
            for (int q = 0; q < 4; q++) c[i][j][q] = 0.0f;

    hgemm_issue(sb, A, B, ldA, ldB, 0, tid);
    CP_COMMIT();
    for (int ch = 0; ch < NC; ch++) {
        if (ch + 1 < NC) {
            hgemm_issue(sb + ((ch + 1) & 1) * HSTG, A, B, ldA, ldB, (ch + 1) * 32, tid);
            CP_COMMIT();
            CP_WAIT1();
        } else {
            CP_WAIT0();
        }
        __syncthreads();
        const u32 st = sb + (ch & 1) * HSTG;
#pragma unroll
        for (int kk = 0; kk < 32; kk += 16) {
            u32 af[2][4], bf[8][2];
#pragma unroll
            for (int s = 0; s < 2; s++)
                ldm4(af[s], st + (wm + s * 16 + rowA) * 80 + kk * 2 + colA);
#pragma unroll
            for (int p = 0; p < 4; p++) {
                u32 t4[4];
                ldm4(t4, st + 10240 + (wn + p * 16 + rowB) * 80 + kk * 2 + colB);
                bf[2 * p][0] = t4[0]; bf[2 * p][1] = t4[1];
                bf[2 * p + 1][0] = t4[2]; bf[2 * p + 1][1] = t4[3];
            }
#pragma unroll
            for (int i = 0; i < 2; i++)
#pragma unroll
                for (int j = 0; j < 8; j++)
                    mma16816h(c[i][j], af[i], bf[j]);
        }
        __syncthreads();
    }
}

// ================ unified prep kernel ================
__device__ __forceinline__ void do_split(
    const float* __restrict__ s, __nv_bfloat16* __restrict__ dh,
    __nv_bfloat16* __restrict__ dl, int blk)
{
    int i = blk * 256 + threadIdx.x;
    float4 v = *(const float4*)(s + (size_t)i * 4);
    __nv_bfloat16 h0, h1, h2, h3, l0, l1, l2, l3;
    split2(v.x, h0, l0); split2(v.y, h1, l1);
    split2(v.z, h2, l2); split2(v.w, h3, l3);
    *(uint2*)(dh + (size_t)i * 4) = make_uint2(bfpack(h0, h1), bfpack(h2, h3));
    *(uint2*)(dl + (size_t)i * 4) = make_uint2(bfpack(l0, l1), bfpack(l2, l3));
}

// transpose 32x32 tile, vectorized 8-byte stores (bank-conflict-free gather)
__device__ __forceinline__ void do_trans_half(
    const float* __restrict__ src, half* __restrict__ d,
    int R, int C, int m, int c0, int r0, float* t)
{
    const int tx = threadIdx.x & 31, ty = threadIdx.x >> 5;
    const float* s = src + (size_t)m * R * C;
#pragma unroll
    for (int j = 0; j < 32; j += 8)
        t[(ty + j) * 33 + tx] = s[(size_t)(r0 + ty + j) * C + c0 + tx];
    __syncthreads();
    const size_t ob = (size_t)m * R * C;
    const int c = threadIdx.x >> 3;        // 0..31 output column
    const int q = (threadIdx.x & 7) * 4;   // output row group (4 rows)
    __align__(8) half h4[4];
#pragma unroll
    for (int k = 0; k < 4; k++)
        h4[k] = __float2half_rn(t[(q + k) * 33 + c]);
    *(uint2*)(d + ob + (size_t)(c0 + c) * R + r0 + q) = *(uint2*)h4;
}

__global__ void __launch_bounds__(256) prep_kernel(
    const float* __restrict__ x, const float* __restrict__ in_w,
    const float* __restrict__ out_w, const float* __restrict__ wi,
    const float* __restrict__ wo)
{
    __shared__ float t[32 * 33];
    const int b = blockIdx.x;
    if (b < 2048)      { do_split(x, g_xh, g_xl, b); }
    else if (b < 2816) { do_split(in_w, g_iwh, g_iwl, b - 2048); }
    else if (b < 3072) { do_split(out_w, g_owh, g_owl, b - 2816); }
    else if (b < 11264) {
        int q = b - 3072;
        int m = q >> 10, rem = q & 1023;
        int cx = rem & 63, cy = rem >> 6;
        do_trans_half(wi, g_w1f, Ddim, Fdim, m, cx * 32, cy * 32, t);
    } else {
        int q = b - 11264;
        int m = q >> 10, rem = q & 1023;
        int cx = rem & 15, cy = rem >> 4;
        do_trans_half(wo, g_w2f, Fdim, Ddim, m, cx * 32, cy * 32, t);
    }
}

// ---------------- QKV GEMM (HMMA), epilogue splits q/k to bf16 ----------------
__device__ __forceinline__ void qkv_store(int m, int cp, float v0, float v1) {
    __nv_bfloat16 h0, l0, h1, l1;
    if (cp < Ddim) {
        split2(v0 * 0.125f, h0, l0);
        split2(v1 * 0.125f, h1, l1);
        *(u32*)(g_qh + (size_t)m * Ddim + cp) = bfpack(h0, h1);
        *(u32*)(g_ql + (size_t)m * Ddim + cp) = bfpack(l0, l1);
    } else if (cp < 2 * Ddim) {
        split2(v0, h0, l0);
        split2(v1, h1, l1);
        *(u32*)(g_kh + (size_t)m * Ddim + cp - Ddim) = bfpack(h0, h1);
        *(u32*)(g_kl + (size_t)m * Ddim + cp - Ddim) = bfpack(l0, l1);
    } else {
        *(float2*)(g_qkv + (size_t)m * QKVW + cp) = make_float2(v0, v1);
    }
}

__global__ void __launch_bounds__(256) qkv_hmma(const float* __restrict__ in_b)
{
    extern __shared__ char sm[];
    const int bm = blockIdx.y * 128, bn = blockIdx.x * 128;
    float c[2][8][4];
    hmma_loop<Ddim>(g_xh + (size_t)bm * Ddim, g_xl + (size_t)bm * Ddim,
                    g_iwh + (size_t)bn * Ddim, g_iwl + (size_t)bn * Ddim,
                    Ddim, Ddim, sm, c);
    const int lane = threadIdx.x & 31, wid = threadIdx.x >> 5;
    const int wm = (wid & 3) * 32, wn = (wid >> 2) * 64;
    const int col = bn + wn + (lane & 3) * 2;
#pragma unroll
    for (int i = 0; i < 2; i++) {
        const int m = bm + wm + i * 16 + (lane >> 2);
#pragma unroll
        for (int j = 0; j < 8; j++) {
            float b0 = in_b[col + j * 8], b1 = in_b[col + j * 8 + 1];
            qkv_store(m, col + j * 8, c[i][j][0] + b0, c[i][j][1] + b1);
            qkv_store(m + 8, col + j * 8, c[i][j][2] + b0, c[i][j][3] + b1);
        }
    }
}

// ---------------- out-proj GEMM (HMMA) ----------------
__global__ void __launch_bounds__(256) outproj_hmma(const float* __restrict__ out_b)
{
    extern __shared__ char sm[];
    const int bm = blockIdx.y * 128, bn = blockIdx.x * 128;
    float c[2][8][4];
    hmma_loop<Ddim>(g_ah + (size_t)bm * Ddim, g_al + (size_t)bm * Ddim,
                    g_owh + (size_t)bn * Ddim, g_owl + (size_t)bn * Ddim,
                    Ddim, Ddim, sm, c);
    const int lane = threadIdx.x & 31, wid = threadIdx.x >> 5;
    const int wm = (wid & 3) * 32, wn = (wid >> 2) * 64;
    const int col = bn + wn + (lane & 3) * 2;
#pragma unroll
    for (int i = 0; i < 2; i++) {
        const int m = bm + wm + i * 16 + (lane >> 2);
#pragma unroll
        for (int j = 0; j < 8; j++) {
            float b0 = out_b[col + j * 8], b1 = out_b[col + j * 8 + 1];
            *(float2*)(g_aout + (size_t)m * Ddim + col + j * 8) =
                make_float2(c[i][j][0] + b0, c[i][j][1] + b1);
            *(float2*)(g_aout + (size_t)(m + 8) * Ddim + col + j * 8) =
                make_float2(c[i][j][2] + b0, c[i][j][3] + b1);
        }
    }
}

// ---------------- V transpose + split ----------------
__global__ void __launch_bounds__(256) v_trans_split_kernel()
{
    __shared__ float t[32][33];
    const int b = blockIdx.z;
    const int s0 = blockIdx.x * 32, d0 = blockIdx.y * 32;
    const int tx = threadIdx.x & 31, ty = threadIdx.x >> 5;
#pragma unroll
    for (int j = 0; j < 32; j += 8)
        t[ty + j][tx] = g_qkv[(size_t)(b * Sdim + s0 + ty + j) * QKVW + 2 * Ddim + d0 + tx];
    __syncthreads();
#pragma unroll
    for (int j = 0; j < 32; j += 8) {
        __nv_bfloat16 h, l;
        split2(t[tx][ty + j], h, l);
        const size_t o = ((size_t)(b * Ddim + d0 + ty + j)) * Sdim + s0 + tx;
        g_vth[o] = h;
        g_vtl[o] = l;
    }
}

// ===== HMMA flash attention, deferred-L streaming softmax (BQ=64, 128 thr) =====
#define FA_STG 36864
#define FA_QOF 73728
#define FA_SMEM 92160

__device__ __forceinline__ void fa_issue(u32 st, int b, int h, int kt, int tid)
{
    int idx = tid;
#pragma unroll
    for (int t = 0; t < 16; t++, idx += 128) {
        int sel = idx >> 9;
        int q = idx & 511;
        int r = q >> 3, kq = q & 7;
        const __nv_bfloat16* src;
        if (sel == 0)      src = g_kh  + (size_t)(b * Sdim + kt * 64 + r) * Ddim + h * HD + kq * 8;
        else if (sel == 1) src = g_kl  + (size_t)(b * Sdim + kt * 64 + r) * Ddim + h * HD + kq * 8;
        else if (sel == 2) src = g_vth + ((size_t)(b * Ddim + h * HD + r)) * Sdim + kt * 64 + kq * 8;
        else               src = g_vtl + ((size_t)(b * Ddim + h * HD + r)) * Sdim + kt * 64 + kq * 8;
        cp16(st + sel * 9216 + r * 144 + kq * 16, src);
    }
}

__global__ void __launch_bounds__(128) flash_attn_hmma()
{
    extern __shared__ char sm[];
    const u32 sb = smem_u32(sm);
    const int tid = threadIdx.x, lane = tid & 31, w = tid >> 5;
    const int qt = blockIdx.x, h = blockIdx.y, b = blockIdx.z;
    const int q0 = qt * 64;
    const int rowA = (lane & 7) + ((lane >> 3) & 1) * 8;
    const int colA = (lane >> 4) * 16;
    const int rowB = (lane & 7) + (lane >> 4) * 8;
    const int colB = ((lane >> 3) & 1) * 16;

    {
        int idx = tid;
#pragma unroll
        for (int t = 0; t < 8; t++, idx += 128) {
            int sel = idx >> 9, q = idx & 511;
            int r = q >> 3, kq = q & 7;
            const __nv_bfloat16* src = (sel ? g_ql : g_qh)
                + (size_t)(b * Sdim + q0 + r) * Ddim + h * HD + kq * 8;
            cp16(sb + FA_QOF + sel * 9216 + r * 144 + kq * 16, src);
        }
        CP_COMMIT();
    }
    fa_issue(sb, b, h, 0, tid);
    CP_COMMIT();
    CP_WAIT1();
    __syncthreads();

    u32 qhf[4][4], qlf[4][4];
#pragma unroll
    for (int kc = 0; kc < 4; kc++) {
        ldm4(qhf[kc], sb + FA_QOF + (w * 16 + rowA) * 144 + kc * 32 + colA);
        ldm4(qlf[kc], sb + FA_QOF + 9216 + (w * 16 + rowA) * 144 + kc * 32 + colA);
    }

    float o[8][4];
#pragma unroll
    for (int j = 0; j < 8; j++)
#pragma unroll
        for (int q = 0; q < 4; q++) o[j][q] = 0.0f;
    float L0 = 0.0f, L1 = 0.0f;

    for (int kt = 0; kt < 16; kt++) {
        if (kt + 1 < 16) {
            fa_issue(sb + ((kt + 1) & 1) * FA_STG, b, h, kt + 1, tid);
            CP_COMMIT();
            CP_WAIT1();
        } else {
            CP_WAIT0();
        }
        __syncthreads();
        const u32 st = sb + (kt & 1) * FA_STG;

        float s[8][4];
#pragma unroll
        for (int j = 0; j < 8; j++)
#pragma unroll
            for (int q = 0; q < 4; q++) s[j][q] = 0.0f;
#pragma unroll
        for (int kc = 0; kc < 4; kc++) {
            u32 kb[8][2], klb[8][2];
#pragma unroll
            for (int p = 0; p < 4; p++) {
                u32 t4[4];
                ldm4(t4, st + (p * 16 + rowB) * 144 + kc * 32 + colB);
                kb[2 * p][0] = t4[0]; kb[2 * p][1] = t4[1];
                kb[2 * p + 1][0] = t4[2]; kb[2 * p + 1][1] = t4[3];
                ldm4(t4, st + 9216 + (p * 16 + rowB) * 144 + kc * 32 + colB);
                klb[2 * p][0] = t4[0]; klb[2 * p][1] = t4[1];
                klb[2 * p + 1][0] = t4[2]; klb[2 * p + 1][1] = t4[3];
            }
#pragma unroll
            for (int j = 0; j < 8; j++) {
                mma16816(s[j], qhf[kc], kb[j]);
                mma16816(s[j], qhf[kc], klb[j]);
                mma16816(s[j], qlf[kc], kb[j]);
            }
        }

#pragma unroll
        for (int j = 0; j < 8; j++) {
            s[j][0] = fexp(s[j][0]);
            s[j][1] = fexp(s[j][1]);
            s[j][2] = fexp(s[j][2]);
            s[j][3] = fexp(s[j][3]);
            L0 += s[j][0] + s[j][1];
            L1 += s[j][2] + s[j][3];
        }

#pragma unroll
        for (int kc = 0; kc < 4; kc++) {
            u32 ph[4], pl[4];
            {
                const float* pA = s[2 * kc];
                const float* pB = s[2 * kc + 1];
                __nv_bfloat16 hh[8], ll[8];
                split2(pA[0], hh[0], ll[0]); split2(pA[1], hh[1], ll[1]);
                split2(pA[2], hh[2], ll[2]); split2(pA[3], hh[3], ll[3]);
                split2(pB[0], hh[4], ll[4]); split2(pB[1], hh[5], ll[5]);
                split2(pB[2], hh[6], ll[6]); split2(pB[3], hh[7], ll[7]);
                ph[0] = bfpack(hh[0], hh[1]); ph[1] = bfpack(hh[2], hh[3]);
                ph[2] = bfpack(hh[4], hh[5]); ph[3] = bfpack(hh[6], hh[7]);
                pl[0] = bfpack(ll[0], ll[1]); pl[1] = bfpack(ll[2], ll[3]);
                pl[2] = bfpack(ll[4], ll[5]); pl[3] = bfpack(ll[6], ll[7]);
            }
            u32 vb[8][2], vlb[8][2];
#pragma unroll
            for (int p = 0; p < 4; p++) {
                u32 t4[4];
                ldm4(t4, st + 18432 + (p * 16 + rowB) * 144 + kc * 32 + colB);
                vb[2 * p][0] = t4[0]; vb[2 * p][1] = t4[1];
                vb[2 * p + 1][0] = t4[2]; vb[2 * p + 1][1] = t4[3];
                ldm4(t4, st + 27648 + (p * 16 + rowB) * 144 + kc * 32 + colB);
                vlb[2 * p][0] = t4[0]; vlb[2 * p][1] = t4[1];
                vlb[2 * p + 1][0] = t4[2]; vlb[2 * p + 1][1] = t4[3];
            }
#pragma unroll
            for (int j = 0; j < 8; j++) {
                mma16816(o[j], ph, vb[j]);
                mma16816(o[j], ph, vlb[j]);
                mma16816(o[j], pl, vb[j]);
            }
        }
        __syncthreads();
    }

    L0 += __shfl_xor_sync(0xffffffffu, L0, 1);
    L0 += __shfl_xor_sync(0xffffffffu, L0, 2);
    L1 += __shfl_xor_sync(0xffffffffu, L1, 1);
    L1 += __shfl_xor_sync(0xffffffffu, L1, 2);

    const float i0 = 1.0f / L0, i1 = 1.0f / L1;
    const int m0 = b * Sdim + q0 + w * 16 + (lane >> 2);
    const int dc = h * HD + (lane & 3) * 2;
#pragma unroll
    for (int j = 0; j < 8; j++) {
        __nv_bfloat16 h0, h1, l0, l1;
        split2(o[j][0] * i0, h0, l0); split2(o[j][1] * i0, h1, l1);
        *(u32*)(g_ah + (size_t)m0 * Ddim + dc + j * 8) = bfpack(h0, h1);
        *(u32*)(g_al + (size_t)m0 * Ddim + dc + j * 8) = bfpack(l0, l1);
        split2(o[j][2] * i1, h0, l0); split2(o[j][3] * i1, h1, l1);
        *(u32*)(g_ah + (size_t)(m0 + 8) * Ddim + dc + j * 8) = bfpack(h0, h1);
        *(u32*)(g_al + (size_t)(m0 + 8) * Ddim + dc + j * 8) = bfpack(l0, l1);
    }
}

// ---------- fused LN1 + router + moe-row zero + mask-row zero ----------
__global__ void __launch_bounds__(128) ln1_router_kernel(
    const float* __restrict__ a, const float* __restrict__ r,
    const float* __restrict__ g, const float* __restrict__ be,
    const float* __restrict__ rw, float* __restrict__ h_out,
    float* __restrict__ logits_out, float* __restrict__ mask_out)
{
    const int n = blockIdx.x;
    const int tid = threadIdx.x;
    __shared__ float red[4], red2[4];
    __shared__ float racc[4][8];
    __shared__ float s_mu, s_rstd;
    if (tid < 8) mask_out[(size_t)n * Edim + tid] = 0.0f;
    const float* ap = a + (size_t)n * Ddim;
    const float* rp = r + (size_t)n * Ddim;
    float v[4];
    float sum = 0.0f, sq = 0.0f;
#pragma unroll
    for (int i = 0; i < 4; i++) {
        v[i] = ap[tid + i * 128] + rp[tid + i * 128];
        sum += v[i];
        sq = fmaf(v[i], v[i], sq);
    }
#pragma unroll
    for (int o = 16; o; o >>= 1) {
        sum += __shfl_xor_sync(0xffffffffu, sum, o);
        sq  += __shfl_xor_sync(0xffffffffu, sq, o);
    }
    if ((tid & 31) == 0) { red[tid >> 5] = sum; red2[tid >> 5] = sq; }
    __syncthreads();
    if (tid == 0) {
        float s = red[0] + red[1] + red[2] + red[3];
        float q = red2[0] + red2[1] + red2[2] + red2[3];
        float mu = s * (1.0f / 512.0f);
        s_mu = mu;
        s_rstd = rsqrtf(q * (1.0f / 512.0f) - mu * mu + 1e-5f);
    }
    __syncthreads();
    float mu = s_mu, rstd = s_rstd;
    float acc[8];
#pragma unroll
    for (int e = 0; e < 8; e++) acc[e] = 0.0f;
#pragma unroll
    for (int i = 0; i < 4; i++) {
        int d = tid + i * 128;
        float hv = (v[i] - mu) * rstd * g[d] + be[d];
        h_out[(size_t)n * Ddim + d] = hv;
        g_moe[(size_t)n * Ddim + d] = 0.0f;
        const float4* rp4 = (const float4*)(rw + d * 8);
        float4 r0 = rp4[0], r1 = rp4[1];
        acc[0] = fmaf(hv, r0.x, acc[0]); acc[1] = fmaf(hv, r0.y, acc[1]);
        acc[2] = fmaf(hv, r0.z, acc[2]); acc[3] = fmaf(hv, r0.w, acc[3]);
        acc[4] = fmaf(hv, r1.x, acc[4]); acc[5] = fmaf(hv, r1.y, acc[5]);
        acc[6] = fmaf(hv, r1.z, acc[6]); acc[7] = fmaf(hv, r1.w, acc[7]);
    }
#pragma unroll
    for (int e = 0; e < 8; e++)
#pragma unroll
        for (int o = 16; o; o >>= 1)
            acc[e] += __shfl_xor_sync(0xffffffffu, acc[e], o);
    if ((tid & 31) == 0)
#pragma unroll
        for (int e = 0; e < 8; e++) racc[tid >> 5][e] = acc[e];
    __syncthreads();
    if (tid == 0) {
        float lg[8];
#pragma unroll
        for (int e = 0; e < 8; e++)
            lg[e] = racc[0][e] + racc[1][e] + racc[2][e] + racc[3][e];
        float m = lg[0]; int arg = 0;
#pragma unroll
        for (int e = 1; e < 8; e++) if (lg[e] > m) { m = lg[e]; arg = e; }
        float s = 0.0f;
#pragma unroll
        for (int e = 0; e < 8; e++) s += __expf(lg[e] - m);
#pragma unroll
        for (int e = 0; e < 8; e++) logits_out[(size_t)n * 8 + e] = lg[e];
        g_idx[n] = arg;
        g_pmax[n] = 1.0f / s;
    }
}

// ---------------- capacity scan: warp-parallel prefix per (batch, expert) ----------------
__global__ void __launch_bounds__(256) capacity_kernel(
    const int* __restrict__ capp, float* __restrict__ mask_out)
{
    const int b = blockIdx.x;
    const int w = threadIdx.x >> 5;
    const int l = threadIdx.x & 31;
    int cap = capp[0];
    if (cap > CAPMAX) cap = CAPMAX;
    const int* idxp = g_idx + b * Sdim;
    const int s0 = l * 32;

    int nl = 0;
#pragma unroll 8
    for (int k = 0; k < 32; k++)
        nl += (idxp[s0 + k] == w) ? 1 : 0;

    int pre = nl;
#pragma unroll
    for (int o = 1; o < 32; o <<= 1) {
        int t = __shfl_up_sync(0xffffffffu, pre, o);
        if (l >= o) pre += t;
    }
    const int total = __shfl_sync(0xffffffffu, pre, 31);
    int pos = pre - nl;

    const int ebase = (b * Edim + w) * CAPMAX;
#pragma unroll 8
    for (int k = 0; k < 32; k++) {
        const int s = s0 + k;
        if (idxp[s] == w) {
            pos++;
            if (pos <= cap) {
                const float pm = g_pmax[b * Sdim + s];
                g_etok[ebase + pos - 1] = s;
                g_escale[ebase + pos - 1] = pm;
                mask_out[((size_t)(b * Sdim + s)) * Edim + w] = pm;
            }
        }
    }
    if (l == 31)
        g_count[b * Edim + w] = total < cap ? total : cap;
}

// ---------------- gather h -> packed fp16 ----------------
__global__ void __launch_bounds__(256) gather_kernel()
{
    const int tid = threadIdx.x;
    const int row = blockIdx.x * 4 + (tid >> 6);
    const int lane = tid & 63;
    const int combo = row >> 8, slot = row & 255;
    __align__(16) half hb[8];
    if (slot < g_count[combo]) {
        const int tok = g_etok[row];
        const int b = combo >> 3;
        const float4* src = (const float4*)(g_h + ((size_t)(b * Sdim + tok)) * Ddim) + lane * 2;
        float4 v0 = src[0], v1 = src[1];
        hb[0] = __float2half_rn(v0.x); hb[1] = __float2half_rn(v0.y);
        hb[2] = __float2half_rn(v0.z); hb[3] = __float2half_rn(v0.w);
        hb[4] = __float2half_rn(v1.x); hb[5] = __float2half_rn(v1.y);
        hb[6] = __float2half_rn(v1.z); hb[7] = __float2half_rn(v1.w);
    } else {
#pragma unroll
        for (int i = 0; i < 8; i++) hb[i] = __float2half_rn(0.0f);
    }
    *(uint4*)(g_hgf + (size_t)row * Ddim + lane * 8) = *(uint4*)hb;
}

// ---------------- FFN1 (fp16 single-pass) ----------------
__global__ void __launch_bounds__(256, 2) ffn1_hmma()
{
    extern __shared__ char sm[];
    const int combo = blockIdx.z;
    const int cnt = g_count[combo];
    const int bm = blockIdx.y * 128;
    if (bm >= cnt) return;
    const int e = combo & 7;
    const int bn = blockIdx.x * 128;
    float c[2][8][4];
    hgemm_loop<Ddim>(g_hgf + (size_t)(combo * CAPMAX + bm) * Ddim,
                     g_w1f + ((size_t)e * Fdim + bn) * Ddim,
                     Ddim, Ddim, sm, c);
    const int lane = threadIdx.x & 31, wid = threadIdx.x >> 5;
    const int wm = (wid & 3) * 32, wn = (wid >> 2) * 64;
    const int col = bn + wn + (lane & 3) * 2;
#pragma unroll
    for (int i = 0; i < 2; i++) {
        const size_t m = combo * CAPMAX + bm + wm + i * 16 + (lane >> 2);
#pragma unroll
        for (int j = 0; j < 8; j++) {
            __half2 p0, p1;
            p0.x = __float2half_rn(gelu_exact(c[i][j][0]));
            p0.y = __float2half_rn(gelu_exact(c[i][j][1]));
            p1.x = __float2half_rn(gelu_exact(c[i][j][2]));
            p1.y = __float2half_rn(gelu_exact(c[i][j][3]));
            *(__half2*)(g_ygf + m * Fdim + col + j * 8) = p0;
            *(__half2*)(g_ygf + (m + 8) * Fdim + col + j * 8) = p1;
        }
    }
}

// ---------------- FFN2 (fp16 single-pass, scatter) ----------------
__global__ void __launch_bounds__(256, 2) ffn2_hmma()
{
    extern __shared__ char sm[];
    const int combo = blockIdx.z;
    const int cnt = g_count[combo];
    const int bm = blockIdx.y * 128;
    if (bm >= cnt) return;
    const int e = combo & 7;
    const int b = combo >> 3;
    const int bn = blockIdx.x * 128;
    float c[2][8][4];
    hgemm_loop<Fdim>(g_ygf + (size_t)(combo * CAPMAX + bm) * Fdim,
                     g_w2f + ((size_t)e * Ddim + bn) * Fdim,
                     Fdim, Fdim, sm, c);
    const int lane = threadIdx.x & 31, wid = threadIdx.x >> 5;
    const int wm = (wid & 3) * 32, wn = (wid >> 2) * 64;
    const int col = bn + wn + (lane & 3) * 2;
#pragma unroll
    for (int i = 0; i < 2; i++) {
        const int m0 = bm + wm + i * 16 + (lane >> 2);
#pragma unroll
        for (int hh = 0; hh < 2; hh++) {
            const int m = m0 + hh * 8;
            if (m < cnt) {
                const int tok = g_etok[combo * CAPMAX + m];
                const float sc = g_escale[combo * CAPMAX + m];
                float* op = g_moe + ((size_t)(b * Sdim + tok)) * Ddim + col;
#pragma unroll
                for (int j = 0; j < 8; j++)
                    *(float2*)(op + j * 8) =
                        make_float2(sc * c[i][j][hh * 2], sc * c[i][j][hh * 2 + 1]);
            }
        }
    }
}

// ---------------- LN2 ----------------
__global__ void __launch_bounds__(128) add_ln_kernel(
    const float* __restrict__ a, const float* __restrict__ r,
    const float* __restrict__ g, const float* __restrict__ be,
    float* __restrict__ out)
{
    const int n = blockIdx.x;
    const int tid = threadIdx.x;
    __shared__ float red[4], red2[4];
    __shared__ float s_mu, s_rstd;
    const float* ap = a + (size_t)n * Ddim;
    const float* rp = r + (size_t)n * Ddim;
    float v[4];
    float sum = 0.0f, sq = 0.0f;
#pragma unroll
    for (int i = 0; i < 4; i++) {
        v[i] = ap[tid + i * 128] + rp[tid + i * 128];
        sum += v[i];
        sq = fmaf(v[i], v[i], sq);
    }
#pragma unroll
    for (int o = 16; o; o >>= 1) {
        sum += __shfl_xor_sync(0xffffffffu, sum, o);
        sq  += __shfl_xor_sync(0xffffffffu, sq, o);
    }
    if ((tid & 31) == 0) { red[tid >> 5] = sum; red2[tid >> 5] = sq; }
    __syncthreads();
    if (tid == 0) {
        float s = red[0] + red[1] + red[2] + red[3];
        float q = red2[0] + red2[1] + red2[2] + red2[3];
        float mu = s * (1.0f / 512.0f);
        s_mu = mu;
        s_rstd = rsqrtf(q * (1.0f / 512.0f) - mu * mu + 1e-5f);
    }
    __syncthreads();
    float mu = s_mu, rstd = s_rstd;
#pragma unroll
    for (int i = 0; i < 4; i++) {
        int d = tid + i * 128;
        out[(size_t)n * Ddim + d] = (v[i] - mu) * rstd * g[d] + be[d];
    }
}

// ---------------- launch ----------------
extern "C" void kernel_launch(void* const* d_in, const int* in_sizes, int n_in,
                              void* d_out, int out_size)
{
    const float* x     = (const float*)d_in[0];
    const float* in_w  = (const float*)d_in[1];
    const float* in_b  = (const float*)d_in[2];
    const float* out_w = (const float*)d_in[3];
    const float* out_b = (const float*)d_in[4];
    const float* ln1g  = (const float*)d_in[5];
    const float* ln1b  = (const float*)d_in[6];
    const float* ln2g  = (const float*)d_in[7];
    const float* ln2b  = (const float*)d_in[8];
    const float* rw    = (const float*)d_in[9];
    const float* wi    = (const float*)d_in[10];
    const float* wo    = (const float*)d_in[11];
    const int*   cap   = (const int*)d_in[12];

    float* out        = (float*)d_out;
    float* logits_out = out + (size_t)NTOK * Ddim;
    float* mask_out   = logits_out + (size_t)NTOK * Edim;

    float *p_aout, *p_h, *p_moe;
    cudaGetSymbolAddress((void**)&p_aout, g_aout);
    cudaGetSymbolAddress((void**)&p_h,    g_h);
    cudaGetSymbolAddress((void**)&p_moe,  g_moe);

    cudaFuncSetAttribute(qkv_hmma,     cudaFuncAttributeMaxDynamicSharedMemorySize, GEMM_SMEM);
    cudaFuncSetAttribute(outproj_hmma, cudaFuncAttributeMaxDynamicSharedMemorySize, GEMM_SMEM);
    cudaFuncSetAttribute(ffn1_hmma,    cudaFuncAttributeMaxDynamicSharedMemorySize, HGEMM_SMEM);
    cudaFuncSetAttribute(ffn2_hmma,    cudaFuncAttributeMaxDynamicSharedMemorySize, HGEMM_SMEM);
    cudaFuncSetAttribute(flash_attn_hmma, cudaFuncAttributeMaxDynamicSharedMemorySize, FA_SMEM);

    // 1) unified prep (vectorized transpose stores)
    prep_kernel<<<19456, 256>>>(x, in_w, out_w, wi, wo);
    // 2) QKV projection
    qkv_hmma<<<dim3(QKVW / 128, NTOK / 128), 256, GEMM_SMEM>>>(in_b);
    // 3) V transpose+split
    v_trans_split_kernel<<<dim3(Sdim / 32, Ddim / 32, Bdim), 256>>>();
    // 4) flash attention
    flash_attn_hmma<<<dim3(Sdim / 64, Hdim, Bdim), 128, FA_SMEM>>>();
    // 5) out-proj
    outproj_hmma<<<dim3(Ddim / 128, NTOK / 128), 256, GEMM_SMEM>>>(out_b);
    // 6) LN1 + router + moe zero + mask zero (fused)
    ln1_router_kernel<<<NTOK, 128>>>(p_aout, x, ln1g, ln1b, rw, p_h, logits_out, mask_out);
    // 7) capacity scan (warp-parallel prefix)
    capacity_kernel<<<Bdim, 256>>>(cap, mask_out);
    // 8) gather
    gather_kernel<<<(32 * CAPMAX) / 4, 256>>>();
    // 9) expert FFN
    ffn1_hmma<<<dim3(Fdim / 128, CAPMAX / 128, 32), 256, HGEMM_SMEM>>>();
    ffn2_hmma<<<dim3(Ddim / 128, CAPMAX / 128, 32), 256, HGEMM_SMEM>>>();
    // 10) LN2
    add_ln_kernel<<<NTOK, 128>>>(p_moe, p_h, ln2g, ln2b, out);
}

// round 15
// speedup vs baseline: 1.0317x; 1.0317x over previous
#include <cuda_runtime.h>
#include <cuda_bf16.h>
#include <cuda_fp16.h>
#include <math.h>

typedef unsigned int u32;
typedef unsigned long long u64;

#define Bdim 4
#define Sdim 1024
#define Ddim 512
#define Fdim 2048
#define Hdim 8
#define Edim 8
#define HD 64
#define NTOK 4096
#define CAPMAX 256
#define QKVW 1536

// ---------------- scratch ----------------
__device__ float g_qkv [NTOK * QKVW];
__device__ float g_aout[NTOK * Ddim];
__device__ float g_h   [NTOK * Ddim];
__device__ float g_moe [NTOK * Ddim];
__device__ __nv_bfloat16 g_xh [NTOK * Ddim], g_xl [NTOK * Ddim];
__device__ __nv_bfloat16 g_iwh[QKVW * Ddim], g_iwl[QKVW * Ddim];
__device__ __nv_bfloat16 g_owh[Ddim * Ddim], g_owl[Ddim * Ddim];
__device__ __nv_bfloat16 g_qh [NTOK * Ddim], g_ql [NTOK * Ddim];
__device__ __nv_bfloat16 g_kh [NTOK * Ddim], g_kl [NTOK * Ddim];
__device__ __nv_bfloat16 g_vth[Bdim * Ddim * Sdim], g_vtl[Bdim * Ddim * Sdim];
__device__ __nv_bfloat16 g_ah [NTOK * Ddim], g_al [NTOK * Ddim];
__device__ half g_hgf[32 * CAPMAX * Ddim];
__device__ half g_ygf[32 * CAPMAX * Fdim];
__device__ half g_w1f[Edim * Fdim * Ddim];
__device__ half g_w2f[Edim * Ddim * Fdim];
__device__ int   g_idx [NTOK];
__device__ float g_pmax[NTOK];
__device__ int   g_etok[32 * CAPMAX];
__device__ float g_escale[32 * CAPMAX];
__device__ int   g_count[32];

// ---------------- helpers ----------------
__device__ __forceinline__ u32 smem_u32(const void* p) {
    u32 a;
    asm("{ .reg .u64 t; cvta.to.shared.u64 t, %1; cvt.u32.u64 %0, t; }" : "=r"(a) : "l"(p));
    return a;
}
__device__ __forceinline__ u32 bfpack(__nv_bfloat16 a, __nv_bfloat16 b) {
    __nv_bfloat162 t; t.x = a; t.y = b; return *(u32*)&t;
}
__device__ __forceinline__ void ldm4(u32 r[4], u32 addr) {
    asm volatile("ldmatrix.sync.aligned.m8n8.x4.shared.b16 {%0,%1,%2,%3}, [%4];"
                 : "=r"(r[0]), "=r"(r[1]), "=r"(r[2]), "=r"(r[3]) : "r"(addr));
}
__device__ __forceinline__ void mma16816(float c[4], const u32 a[4], const u32 b[2]) {
    asm volatile(
        "mma.sync.aligned.m16n8k16.row.col.f32.bf16.bf16.f32 "
        "{%0,%1,%2,%3}, {%4,%5,%6,%7}, {%8,%9}, {%0,%1,%2,%3};"
        : "+f"(c[0]), "+f"(c[1]), "+f"(c[2]), "+f"(c[3])
        : "r"(a[0]), "r"(a[1]), "r"(a[2]), "r"(a[3]), "r"(b[0]), "r"(b[1]));
}
__device__ __forceinline__ void mma16816h(float c[4], const u32 a[4], const u32 b[2]) {
    asm volatile(
        "mma.sync.aligned.m16n8k16.row.col.f32.f16.f16.f32 "
        "{%0,%1,%2,%3}, {%4,%5,%6,%7}, {%8,%9}, {%0,%1,%2,%3};"
        : "+f"(c[0]), "+f"(c[1]), "+f"(c[2]), "+f"(c[3])
        : "r"(a[0]), "r"(a[1]), "r"(a[2]), "r"(a[3]), "r"(b[0]), "r"(b[1]));
}
__device__ __forceinline__ void cp16(u32 dst, const void* src) {
    asm volatile("cp.async.cg.shared.global [%0], [%1], 16;" :: "r"(dst), "l"(src));
}
#define CP_COMMIT() asm volatile("cp.async.commit_group;" ::: "memory")
#define CP_WAIT1()  asm volatile("cp.async.wait_group 1;" ::: "memory")
#define CP_WAIT0()  asm volatile("cp.async.wait_group 0;" ::: "memory")
__device__ __forceinline__ float gelu_exact(float x) {
    return 0.5f * x * (1.0f + erff(x * 0.70710678118654752f));
}
__device__ __forceinline__ void split2(float v, __nv_bfloat16& h, __nv_bfloat16& l) {
    h = __float2bfloat16(v);
    l = __float2bfloat16(v - __bfloat162float(h));
}
__device__ __forceinline__ float fexp(float x) {
    float y = fmaxf(x * 1.4426950408889634f, -126.0f);
    int i = __float2int_rn(y);
    float f = y - (float)i;
    float p = 0.0013333558146f;
    p = fmaf(p, f, 0.0096181291076f);
    p = fmaf(p, f, 0.0555041086648f);
    p = fmaf(p, f, 0.2402265069591f);
    p = fmaf(p, f, 0.6931471805599f);
    p = fmaf(p, f, 1.0f);
    return __int_as_float(__float_as_int(p) + (i << 23));
}

// ========== pipelined HMMA bf16-split NT mainloop (128x128, 256 thr) ==========
#define GSTG 40960
#define GEMM_SMEM (2 * GSTG)

__device__ __forceinline__ void gemm_issue(
    u32 st, const __nv_bfloat16* Ah, const __nv_bfloat16* Al,
    const __nv_bfloat16* Bh, const __nv_bfloat16* Bl,
    int ldA, int ldB, int k0, int tid)
{
    int idx = tid;
#pragma unroll
    for (int t = 0; t < 8; t++, idx += 256) {
        int sel = idx >> 9;
        int q = idx & 511;
        int r = q >> 2, kq = q & 3;
        const __nv_bfloat16* src = (sel == 0 ? Ah : sel == 1 ? Al : sel == 2 ? Bh : Bl);
        int ld = (sel < 2) ? ldA : ldB;
        cp16(st + sel * 10240 + r * 80 + kq * 16, src + (size_t)r * ld + k0 + kq * 8);
    }
}

template<int K>
__device__ __forceinline__ void hmma_loop(
    const __nv_bfloat16* Ah, const __nv_bfloat16* Al,
    const __nv_bfloat16* Bh, const __nv_bfloat16* Bl,
    int ldA, int ldB, char* smbase, float (&c)[2][8][4])
{
    const int tid = threadIdx.x, lane = tid & 31, wid = tid >> 5;
    const int wm = (wid & 3) * 32, wn = (wid >> 2) * 64;
    const int rowA = (lane & 7) + ((lane >> 3) & 1) * 8;
    const int colA = (lane >> 4) * 16;
    const int rowB = (lane & 7) + (lane >> 4) * 8;
    const int colB = ((lane >> 3) & 1) * 16;
    const u32 sb = smem_u32(smbase);
    constexpr int NC = K / 32;

#pragma unroll
    for (int i = 0; i < 2; i++)
#pragma unroll
        for (int j = 0; j < 8; j++)
#pragma unroll
            for (int q = 0; q < 4; q++) c[i][j][q] = 0.0f;

    gemm_issue(sb, Ah, Al, Bh, Bl, ldA, ldB, 0, tid);
    CP_COMMIT();
    for (int ch = 0; ch < NC; ch++) {
        if (ch + 1 < NC) {
            gemm_issue(sb + ((ch + 1) & 1) * GSTG, Ah, Al, Bh, Bl, ldA, ldB, (ch + 1) * 32, tid);
            CP_COMMIT();
            CP_WAIT1();
        } else {
            CP_WAIT0();
        }
        __syncthreads();
        const u32 st = sb + (ch & 1) * GSTG;
#pragma unroll
        for (int kk = 0; kk < 32; kk += 16) {
            u32 ah[2][4], al[2][4], bh[8][2], bl[8][2];
#pragma unroll
            for (int s = 0; s < 2; s++) {
                ldm4(ah[s], st + (wm + s * 16 + rowA) * 80 + kk * 2 + colA);
                ldm4(al[s], st + 10240 + (wm + s * 16 + rowA) * 80 + kk * 2 + colA);
            }
#pragma unroll
            for (int p = 0; p < 4; p++) {
                u32 t4[4];
                ldm4(t4, st + 20480 + (wn + p * 16 + rowB) * 80 + kk * 2 + colB);
                bh[2 * p][0] = t4[0]; bh[2 * p][1] = t4[1];
                bh[2 * p + 1][0] = t4[2]; bh[2 * p + 1][1] = t4[3];
                ldm4(t4, st + 30720 + (wn + p * 16 + rowB) * 80 + kk * 2 + colB);
                bl[2 * p][0] = t4[0]; bl[2 * p][1] = t4[1];
                bl[2 * p + 1][0] = t4[2]; bl[2 * p + 1][1] = t4[3];
            }
#pragma unroll
            for (int i = 0; i < 2; i++)
#pragma unroll
                for (int j = 0; j < 8; j++) {
                    mma16816(c[i][j], ah[i], bh[j]);
                    mma16816(c[i][j], ah[i], bl[j]);
                    mma16816(c[i][j], al[i], bh[j]);
                }
        }
        __syncthreads();
    }
}

// ========== pipelined fp16 single-pass NT mainloop (128x128, 256 thr) ==========
#define HSTG 20480
#define HGEMM_SMEM (2 * HSTG)

__device__ __forceinline__ void hgemm_issue(
    u32 st, const half* A, const half* B, int ldA, int ldB, int k0, int tid)
{
    int idx = tid;
#pragma unroll
    for (int t = 0; t < 4; t++, idx += 256) {
        int sel = idx >> 9;
        int q = idx & 511;
        int r = q >> 2, kq = q & 3;
        const half* src = sel ? B : A;
        int ld = sel ? ldB : ldA;
        cp16(st + sel * 10240 + r * 80 + kq * 16, src + (size_t)r * ld + k0 + kq * 8);
    }
}

template<int K>
__device__ __forceinline__ void hgemm_loop(
    const half* A, const half* B, int ldA, int ldB, char* smbase, float (&c)[2][8][4])
{
    const int tid = threadIdx.x, lane = tid & 31, wid = tid >> 5;
    const int wm = (wid & 3) * 32, wn = (wid >> 2) * 64;
    const int rowA = (lane & 7) + ((lane >> 3) & 1) * 8;
    const int colA = (lane >> 4) * 16;
    const int rowB = (lane & 7) + (lane >> 4) * 8;
    const int colB = ((lane >> 3) & 1) * 16;
    const u32 sb = smem_u32(smbase);
    constexpr int NC = K / 32;

#pragma unroll
    for (int i = 0; i < 2; i++)
#pragma unroll
        for (int j = 0; j < 8; j++)
#pragma unroll
            for (int q = 0; q < 4; q++) c[i][j][q] = 0.0f;

    hgemm_issue(sb, A, B, ldA, ldB, 0, tid);
    CP_COMMIT();
    for (int ch = 0; ch < NC; ch++) {
        if (ch + 1 < NC) {
            hgemm_issue(sb + ((ch + 1) & 1) * HSTG, A, B, ldA, ldB, (ch + 1) * 32, tid);
            CP_COMMIT();
            CP_WAIT1();
        } else {
            CP_WAIT0();
        }
        __syncthreads();
        const u32 st = sb + (ch & 1) * HSTG;
#pragma unroll
        for (int kk = 0; kk < 32; kk += 16) {
            u32 af[2][4], bf[8][2];
#pragma unroll
            for (int s = 0; s < 2; s++)
                ldm4(af[s], st + (wm + s * 16 + rowA) * 80 + kk * 2 + colA);
#pragma unroll
            for (int p = 0; p < 4; p++) {
                u32 t4[4];
                ldm4(t4, st + 10240 + (wn + p * 16 + rowB) * 80 + kk * 2 + colB);
                bf[2 * p][0] = t4[0]; bf[2 * p][1] = t4[1];
                bf[2 * p + 1][0] = t4[2]; bf[2 * p + 1][1] = t4[3];
            }
#pragma unroll
            for (int i = 0; i < 2; i++)
#pragma unroll
                for (int j = 0; j < 8; j++)
                    mma16816h(c[i][j], af[i], bf[j]);
        }
        __syncthreads();
    }
}

// ================ unified prep kernel ================
__device__ __forceinline__ void do_split(
    const float* __restrict__ s, __nv_bfloat16* __restrict__ dh,
    __nv_bfloat16* __restrict__ dl, int blk)
{
    int i = blk * 256 + threadIdx.x;
    float4 v = *(const float4*)(s + (size_t)i * 4);
    __nv_bfloat16 h0, h1, h2, h3, l0, l1, l2, l3;
    split2(v.x, h0, l0); split2(v.y, h1, l1);
    split2(v.z, h2, l2); split2(v.w, h3, l3);
    *(uint2*)(dh + (size_t)i * 4) = make_uint2(bfpack(h0, h1), bfpack(h2, h3));
    *(uint2*)(dl + (size_t)i * 4) = make_uint2(bfpack(l0, l1), bfpack(l2, l3));
}

__device__ __forceinline__ void do_trans_half(
    const float* __restrict__ src, half* __restrict__ d,
    int R, int C, int m, int c0, int r0, float* t)
{
    const int tx = threadIdx.x & 31, ty = threadIdx.x >> 5;
    const float* s = src + (size_t)m * R * C;
#pragma unroll
    for (int j = 0; j < 32; j += 8)
        t[(ty + j) * 33 + tx] = s[(size_t)(r0 + ty + j) * C + c0 + tx];
    __syncthreads();
    const size_t ob = (size_t)m * R * C;
    const int c = threadIdx.x >> 3;
    const int q = (threadIdx.x & 7) * 4;
    __align__(8) half h4[4];
#pragma unroll
    for (int k = 0; k < 4; k++)
        h4[k] = __float2half_rn(t[(q + k) * 33 + c]);
    *(uint2*)(d + ob + (size_t)(c0 + c) * R + r0 + q) = *(uint2*)h4;
}

__global__ void __launch_bounds__(256) prep_kernel(
    const float* __restrict__ x, const float* __restrict__ in_w,
    const float* __restrict__ out_w, const float* __restrict__ wi,
    const float* __restrict__ wo)
{
    __shared__ float t[32 * 33];
    const int b = blockIdx.x;
    if (b < 2048)      { do_split(x, g_xh, g_xl, b); }
    else if (b < 2816) { do_split(in_w, g_iwh, g_iwl, b - 2048); }
    else if (b < 3072) { do_split(out_w, g_owh, g_owl, b - 2816); }
    else if (b < 11264) {
        int q = b - 3072;
        int m = q >> 10, rem = q & 1023;
        int cx = rem & 63, cy = rem >> 6;
        do_trans_half(wi, g_w1f, Ddim, Fdim, m, cx * 32, cy * 32, t);
    } else {
        int q = b - 11264;
        int m = q >> 10, rem = q & 1023;
        int cx = rem & 15, cy = rem >> 4;
        do_trans_half(wo, g_w2f, Fdim, Ddim, m, cx * 32, cy * 32, t);
    }
}

// ---------------- QKV GEMM (HMMA), epilogue splits q/k to bf16 ----------------
__device__ __forceinline__ void qkv_store(int m, int cp, float v0, float v1) {
    __nv_bfloat16 h0, l0, h1, l1;
    if (cp < Ddim) {
        split2(v0 * 0.125f, h0, l0);
        split2(v1 * 0.125f, h1, l1);
        *(u32*)(g_qh + (size_t)m * Ddim + cp) = bfpack(h0, h1);
        *(u32*)(g_ql + (size_t)m * Ddim + cp) = bfpack(l0, l1);
    } else if (cp < 2 * Ddim) {
        split2(v0, h0, l0);
        split2(v1, h1, l1);
        *(u32*)(g_kh + (size_t)m * Ddim + cp - Ddim) = bfpack(h0, h1);
        *(u32*)(g_kl + (size_t)m * Ddim + cp - Ddim) = bfpack(l0, l1);
    } else {
        *(float2*)(g_qkv + (size_t)m * QKVW + cp) = make_float2(v0, v1);
    }
}

__global__ void __launch_bounds__(256) qkv_hmma(const float* __restrict__ in_b)
{
    extern __shared__ char sm[];
    const int bm = blockIdx.y * 128, bn = blockIdx.x * 128;
    float c[2][8][4];
    hmma_loop<Ddim>(g_xh + (size_t)bm * Ddim, g_xl + (size_t)bm * Ddim,
                    g_iwh + (size_t)bn * Ddim, g_iwl + (size_t)bn * Ddim,
                    Ddim, Ddim, sm, c);
    const int lane = threadIdx.x & 31, wid = threadIdx.x >> 5;
    const int wm = (wid & 3) * 32, wn = (wid >> 2) * 64;
    const int col = bn + wn + (lane & 3) * 2;
#pragma unroll
    for (int i = 0; i < 2; i++) {
        const int m = bm + wm + i * 16 + (lane >> 2);
#pragma unroll
        for (int j = 0; j < 8; j++) {
            float b0 = in_b[col + j * 8], b1 = in_b[col + j * 8 + 1];
            qkv_store(m, col + j * 8, c[i][j][0] + b0, c[i][j][1] + b1);
            qkv_store(m + 8, col + j * 8, c[i][j][2] + b0, c[i][j][3] + b1);
        }
    }
}

// ---------------- out-proj GEMM (HMMA) ----------------
__global__ void __launch_bounds__(256) outproj_hmma(const float* __restrict__ out_b)
{
    extern __shared__ char sm[];
    const int bm = blockIdx.y * 128, bn = blockIdx.x * 128;
    float c[2][8][4];
    hmma_loop<Ddim>(g_ah + (size_t)bm * Ddim, g_al + (size_t)bm * Ddim,
                    g_owh + (size_t)bn * Ddim, g_owl + (size_t)bn * Ddim,
                    Ddim, Ddim, sm, c);
    const int lane = threadIdx.x & 31, wid = threadIdx.x >> 5;
    const int wm = (wid & 3) * 32, wn = (wid >> 2) * 64;
    const int col = bn + wn + (lane & 3) * 2;
#pragma unroll
    for (int i = 0; i < 2; i++) {
        const int m = bm + wm + i * 16 + (lane >> 2);
#pragma unroll
        for (int j = 0; j < 8; j++) {
            float b0 = out_b[col + j * 8], b1 = out_b[col + j * 8 + 1];
            *(float2*)(g_aout + (size_t)m * Ddim + col + j * 8) =
                make_float2(c[i][j][0] + b0, c[i][j][1] + b1);
            *(float2*)(g_aout + (size_t)(m + 8) * Ddim + col + j * 8) =
                make_float2(c[i][j][2] + b0, c[i][j][3] + b1);
        }
    }
}

// ---------------- V transpose + split ----------------
__global__ void __launch_bounds__(256) v_trans_split_kernel()
{
    __shared__ float t[32][33];
    const int b = blockIdx.z;
    const int s0 = blockIdx.x * 32, d0 = blockIdx.y * 32;
    const int tx = threadIdx.x & 31, ty = threadIdx.x >> 5;
#pragma unroll
    for (int j = 0; j < 32; j += 8)
        t[ty + j][tx] = g_qkv[(size_t)(b * Sdim + s0 + ty + j) * QKVW + 2 * Ddim + d0 + tx];
    __syncthreads();
#pragma unroll
    for (int j = 0; j < 32; j += 8) {
        __nv_bfloat16 h, l;
        split2(t[tx][ty + j], h, l);
        const size_t o = ((size_t)(b * Ddim + d0 + ty + j)) * Sdim + s0 + tx;
        g_vth[o] = h;
        g_vtl[o] = l;
    }
}

// ===== HMMA flash attention, deferred-L streaming softmax (BQ=64, 128 thr, 2 CTA/SM) =====
#define FA_STG 36864
#define FA_QOF 73728
#define FA_SMEM 92160

__device__ __forceinline__ void fa_issue(u32 st, int b, int h, int kt, int tid)
{
    int idx = tid;
#pragma unroll
    for (int t = 0; t < 16; t++, idx += 128) {
        int sel = idx >> 9;
        int q = idx & 511;
        int r = q >> 3, kq = q & 7;
        const __nv_bfloat16* src;
        if (sel == 0)      src = g_kh  + (size_t)(b * Sdim + kt * 64 + r) * Ddim + h * HD + kq * 8;
        else if (sel == 1) src = g_kl  + (size_t)(b * Sdim + kt * 64 + r) * Ddim + h * HD + kq * 8;
        else if (sel == 2) src = g_vth + ((size_t)(b * Ddim + h * HD + r)) * Sdim + kt * 64 + kq * 8;
        else               src = g_vtl + ((size_t)(b * Ddim + h * HD + r)) * Sdim + kt * 64 + kq * 8;
        cp16(st + sel * 9216 + r * 144 + kq * 16, src);
    }
}

__global__ void __launch_bounds__(128, 2) flash_attn_hmma()
{
    extern __shared__ char sm[];
    const u32 sb = smem_u32(sm);
    const int tid = threadIdx.x, lane = tid & 31, w = tid >> 5;
    const int qt = blockIdx.x, h = blockIdx.y, b = blockIdx.z;
    const int q0 = qt * 64;
    const int rowA = (lane & 7) + ((lane >> 3) & 1) * 8;
    const int colA = (lane >> 4) * 16;
    const int rowB = (lane & 7) + (lane >> 4) * 8;
    const int colB = ((lane >> 3) & 1) * 16;

    {
        int idx = tid;
#pragma unroll
        for (int t = 0; t < 8; t++, idx += 128) {
            int sel = idx >> 9, q = idx & 511;
            int r = q >> 3, kq = q & 7;
            const __nv_bfloat16* src = (sel ? g_ql : g_qh)
                + (size_t)(b * Sdim + q0 + r) * Ddim + h * HD + kq * 8;
            cp16(sb + FA_QOF + sel * 9216 + r * 144 + kq * 16, src);
        }
        CP_COMMIT();
    }
    fa_issue(sb, b, h, 0, tid);
    CP_COMMIT();
    CP_WAIT1();
    __syncthreads();

    u32 qhf[4][4], qlf[4][4];
#pragma unroll
    for (int kc = 0; kc < 4; kc++) {
        ldm4(qhf[kc], sb + FA_QOF + (w * 16 + rowA) * 144 + kc * 32 + colA);
        ldm4(qlf[kc], sb + FA_QOF + 9216 + (w * 16 + rowA) * 144 + kc * 32 + colA);
    }

    float o[8][4];
#pragma unroll
    for (int j = 0; j < 8; j++)
#pragma unroll
        for (int q = 0; q < 4; q++) o[j][q] = 0.0f;
    float L0 = 0.0f, L1 = 0.0f;

    for (int kt = 0; kt < 16; kt++) {
        if (kt + 1 < 16) {
            fa_issue(sb + ((kt + 1) & 1) * FA_STG, b, h, kt + 1, tid);
            CP_COMMIT();
            CP_WAIT1();
        } else {
            CP_WAIT0();
        }
        __syncthreads();
        const u32 st = sb + (kt & 1) * FA_STG;

        float s[8][4];
#pragma unroll
        for (int j = 0; j < 8; j++)
#pragma unroll
            for (int q = 0; q < 4; q++) s[j][q] = 0.0f;
#pragma unroll
        for (int kc = 0; kc < 4; kc++) {
            u32 kb[8][2], klb[8][2];
#pragma unroll
            for (int p = 0; p < 4; p++) {
                u32 t4[4];
                ldm4(t4, st + (p * 16 + rowB) * 144 + kc * 32 + colB);
                kb[2 * p][0] = t4[0]; kb[2 * p][1] = t4[1];
                kb[2 * p + 1][0] = t4[2]; kb[2 * p + 1][1] = t4[3];
                ldm4(t4, st + 9216 + (p * 16 + rowB) * 144 + kc * 32 + colB);
                klb[2 * p][0] = t4[0]; klb[2 * p][1] = t4[1];
                klb[2 * p + 1][0] = t4[2]; klb[2 * p + 1][1] = t4[3];
            }
#pragma unroll
            for (int j = 0; j < 8; j++) {
                mma16816(s[j], qhf[kc], kb[j]);
                mma16816(s[j], qhf[kc], klb[j]);
                mma16816(s[j], qlf[kc], kb[j]);
            }
        }

#pragma unroll
        for (int j = 0; j < 8; j++) {
            s[j][0] = fexp(s[j][0]);
            s[j][1] = fexp(s[j][1]);
            s[j][2] = fexp(s[j][2]);
            s[j][3] = fexp(s[j][3]);
            L0 += s[j][0] + s[j][1];
            L1 += s[j][2] + s[j][3];
        }

#pragma unroll
        for (int kc = 0; kc < 4; kc++) {
            u32 ph[4], pl[4];
            {
                const float* pA = s[2 * kc];
                const float* pB = s[2 * kc + 1];
                __nv_bfloat16 hh[8], ll[8];
                split2(pA[0], hh[0], ll[0]); split2(pA[1], hh[1], ll[1]);
                split2(pA[2], hh[2], ll[2]); split2(pA[3], hh[3], ll[3]);
                split2(pB[0], hh[4], ll[4]); split2(pB[1], hh[5], ll[5]);
                split2(pB[2], hh[6], ll[6]); split2(pB[3], hh[7], ll[7]);
                ph[0] = bfpack(hh[0], hh[1]); ph[1] = bfpack(hh[2], hh[3]);
                ph[2] = bfpack(hh[4], hh[5]); ph[3] = bfpack(hh[6], hh[7]);
                pl[0] = bfpack(ll[0], ll[1]); pl[1] = bfpack(ll[2], ll[3]);
                pl[2] = bfpack(ll[4], ll[5]); pl[3] = bfpack(ll[6], ll[7]);
            }
            u32 vb[8][2], vlb[8][2];
#pragma unroll
            for (int p = 0; p < 4; p++) {
                u32 t4[4];
                ldm4(t4, st + 18432 + (p * 16 + rowB) * 144 + kc * 32 + colB);
                vb[2 * p][0] = t4[0]; vb[2 * p][1] = t4[1];
                vb[2 * p + 1][0] = t4[2]; vb[2 * p + 1][1] = t4[3];
                ldm4(t4, st + 27648 + (p * 16 + rowB) * 144 + kc * 32 + colB);
                vlb[2 * p][0] = t4[0]; vlb[2 * p][1] = t4[1];
                vlb[2 * p + 1][0] = t4[2]; vlb[2 * p + 1][1] = t4[3];
            }
#pragma unroll
            for (int j = 0; j < 8; j++) {
                mma16816(o[j], ph, vb[j]);
                mma16816(o[j], ph, vlb[j]);
                mma16816(o[j], pl, vb[j]);
            }
        }
        __syncthreads();
    }

    L0 += __shfl_xor_sync(0xffffffffu, L0, 1);
    L0 += __shfl_xor_sync(0xffffffffu, L0, 2);
    L1 += __shfl_xor_sync(0xffffffffu, L1, 1);
    L1 += __shfl_xor_sync(0xffffffffu, L1, 2);

    const float i0 = 1.0f / L0, i1 = 1.0f / L1;
    const int m0 = b * Sdim + q0 + w * 16 + (lane >> 2);
    const int dc = h * HD + (lane & 3) * 2;
#pragma unroll
    for (int j = 0; j < 8; j++) {
        __nv_bfloat16 h0, h1, l0, l1;
        split2(o[j][0] * i0, h0, l0); split2(o[j][1] * i0, h1, l1);
        *(u32*)(g_ah + (size_t)m0 * Ddim + dc + j * 8) = bfpack(h0, h1);
        *(u32*)(g_al + (size_t)m0 * Ddim + dc + j * 8) = bfpack(l0, l1);
        split2(o[j][2] * i1, h0, l0); split2(o[j][3] * i1, h1, l1);
        *(u32*)(g_ah + (size_t)(m0 + 8) * Ddim + dc + j * 8) = bfpack(h0, h1);
        *(u32*)(g_al + (size_t)(m0 + 8) * Ddim + dc + j * 8) = bfpack(l0, l1);
    }
}

// ---------- fused LN1 + router + moe-row zero + mask-row zero ----------
__global__ void __launch_bounds__(128) ln1_router_kernel(
    const float* __restrict__ a, const float* __restrict__ r,
    const float* __restrict__ g, const float* __restrict__ be,
    const float* __restrict__ rw, float* __restrict__ h_out,
    float* __restrict__ logits_out, float* __restrict__ mask_out)
{
    const int n = blockIdx.x;
    const int tid = threadIdx.x;
    __shared__ float red[4], red2[4];
    __shared__ float racc[4][8];
    __shared__ float s_mu, s_rstd;
    if (tid < 8) mask_out[(size_t)n * Edim + tid] = 0.0f;
    const float* ap = a + (size_t)n * Ddim;
    const float* rp = r + (size_t)n * Ddim;
    float v[4];
    float sum = 0.0f, sq = 0.0f;
#pragma unroll
    for (int i = 0; i < 4; i++) {
        v[i] = ap[tid + i * 128] + rp[tid + i * 128];
        sum += v[i];
        sq = fmaf(v[i], v[i], sq);
    }
#pragma unroll
    for (int o = 16; o; o >>= 1) {
        sum += __shfl_xor_sync(0xffffffffu, sum, o);
        sq  += __shfl_xor_sync(0xffffffffu, sq, o);
    }
    if ((tid & 31) == 0) { red[tid >> 5] = sum; red2[tid >> 5] = sq; }
    __syncthreads();
    if (tid == 0) {
        float s = red[0] + red[1] + red[2] + red[3];
        float q = red2[0] + red2[1] + red2[2] + red2[3];
        float mu = s * (1.0f / 512.0f);
        s_mu = mu;
        s_rstd = rsqrtf(q * (1.0f / 512.0f) - mu * mu + 1e-5f);
    }
    __syncthreads();
    float mu = s_mu, rstd = s_rstd;
    float acc[8];
#pragma unroll
    for (int e = 0; e < 8; e++) acc[e] = 0.0f;
#pragma unroll
    for (int i = 0; i < 4; i++) {
        int d = tid + i * 128;
        float hv = (v[i] - mu) * rstd * g[d] + be[d];
        h_out[(size_t)n * Ddim + d] = hv;
        g_moe[(size_t)n * Ddim + d] = 0.0f;
        const float4* rp4 = (const float4*)(rw + d * 8);
        float4 r0 = rp4[0], r1 = rp4[1];
        acc[0] = fmaf(hv, r0.x, acc[0]); acc[1] = fmaf(hv, r0.y, acc[1]);
        acc[2] = fmaf(hv, r0.z, acc[2]); acc[3] = fmaf(hv, r0.w, acc[3]);
        acc[4] = fmaf(hv, r1.x, acc[4]); acc[5] = fmaf(hv, r1.y, acc[5]);
        acc[6] = fmaf(hv, r1.z, acc[6]); acc[7] = fmaf(hv, r1.w, acc[7]);
    }
#pragma unroll
    for (int e = 0; e < 8; e++)
#pragma unroll
        for (int o = 16; o; o >>= 1)
            acc[e] += __shfl_xor_sync(0xffffffffu, acc[e], o);
    if ((tid & 31) == 0)
#pragma unroll
        for (int e = 0; e < 8; e++) racc[tid >> 5][e] = acc[e];
    __syncthreads();
    if (tid == 0) {
        float lg[8];
#pragma unroll
        for (int e = 0; e < 8; e++)
            lg[e] = racc[0][e] + racc[1][e] + racc[2][e] + racc[3][e];
        float m = lg[0]; int arg = 0;
#pragma unroll
        for (int e = 1; e < 8; e++) if (lg[e] > m) { m = lg[e]; arg = e; }
        float s = 0.0f;
#pragma unroll
        for (int e = 0; e < 8; e++) s += __expf(lg[e] - m);
#pragma unroll
        for (int e = 0; e < 8; e++) logits_out[(size_t)n * 8 + e] = lg[e];
        g_idx[n] = arg;
        g_pmax[n] = 1.0f / s;
    }
}

// ---------------- capacity scan: warp-parallel prefix per (batch, expert) ----------------
__global__ void __launch_bounds__(256) capacity_kernel(
    const int* __restrict__ capp, float* __restrict__ mask_out)
{
    const int b = blockIdx.x;
    const int w = threadIdx.x >> 5;
    const int l = threadIdx.x & 31;
    int cap = capp[0];
    if (cap > CAPMAX) cap = CAPMAX;
    const int* idxp = g_idx + b * Sdim;
    const int s0 = l * 32;

    int nl = 0;
#pragma unroll 8
    for (int k = 0; k < 32; k++)
        nl += (idxp[s0 + k] == w) ? 1 : 0;

    int pre = nl;
#pragma unroll
    for (int o = 1; o < 32; o <<= 1) {
        int t = __shfl_up_sync(0xffffffffu, pre, o);
        if (l >= o) pre += t;
    }
    const int total = __shfl_sync(0xffffffffu, pre, 31);
    int pos = pre - nl;

    const int ebase = (b * Edim + w) * CAPMAX;
#pragma unroll 8
    for (int k = 0; k < 32; k++) {
        const int s = s0 + k;
        if (idxp[s] == w) {
            pos++;
            if (pos <= cap) {
                const float pm = g_pmax[b * Sdim + s];
                g_etok[ebase + pos - 1] = s;
                g_escale[ebase + pos - 1] = pm;
                mask_out[((size_t)(b * Sdim + s)) * Edim + w] = pm;
            }
        }
    }
    if (l == 31)
        g_count[b * Edim + w] = total < cap ? total : cap;
}

// ---------------- gather h -> packed fp16 ----------------
__global__ void __launch_bounds__(256) gather_kernel()
{
    const int tid = threadIdx.x;
    const int row = blockIdx.x * 4 + (tid >> 6);
    const int lane = tid & 63;
    const int combo = row >> 8, slot = row & 255;
    __align__(16) half hb[8];
    if (slot < g_count[combo]) {
        const int tok = g_etok[row];
        const int b = combo >> 3;
        const float4* src = (const float4*)(g_h + ((size_t)(b * Sdim + tok)) * Ddim) + lane * 2;
        float4 v0 = src[0], v1 = src[1];
        hb[0] = __float2half_rn(v0.x); hb[1] = __float2half_rn(v0.y);
        hb[2] = __float2half_rn(v0.z); hb[3] = __float2half_rn(v0.w);
        hb[4] = __float2half_rn(v1.x); hb[5] = __float2half_rn(v1.y);
        hb[6] = __float2half_rn(v1.z); hb[7] = __float2half_rn(v1.w);
    } else {
#pragma unroll
        for (int i = 0; i < 8; i++) hb[i] = __float2half_rn(0.0f);
    }
    *(uint4*)(g_hgf + (size_t)row * Ddim + lane * 8) = *(uint4*)hb;
}

// ---------------- FFN1 (fp16 single-pass) ----------------
__global__ void __launch_bounds__(256, 2) ffn1_hmma()
{
    extern __shared__ char sm[];
    const int combo = blockIdx.z;
    const int cnt = g_count[combo];
    const int bm = blockIdx.y * 128;
    if (bm >= cnt) return;
    const int e = combo & 7;
    const int bn = blockIdx.x * 128;
    float c[2][8][4];
    hgemm_loop<Ddim>(g_hgf + (size_t)(combo * CAPMAX + bm) * Ddim,
                     g_w1f + ((size_t)e * Fdim + bn) * Ddim,
                     Ddim, Ddim, sm, c);
    const int lane = threadIdx.x & 31, wid = threadIdx.x >> 5;
    const int wm = (wid & 3) * 32, wn = (wid >> 2) * 64;
    const int col = bn + wn + (lane & 3) * 2;
#pragma unroll
    for (int i = 0; i < 2; i++) {
        const size_t m = combo * CAPMAX + bm + wm + i * 16 + (lane >> 2);
#pragma unroll
        for (int j = 0; j < 8; j++) {
            __half2 p0, p1;
            p0.x = __float2half_rn(gelu_exact(c[i][j][0]));
            p0.y = __float2half_rn(gelu_exact(c[i][j][1]));
            p1.x = __float2half_rn(gelu_exact(c[i][j][2]));
            p1.y = __float2half_rn(gelu_exact(c[i][j][3]));
            *(__half2*)(g_ygf + m * Fdim + col + j * 8) = p0;
            *(__half2*)(g_ygf + (m + 8) * Fdim + col + j * 8) = p1;
        }
    }
}

// ---------------- FFN2 (fp16 single-pass, scatter) ----------------
__global__ void __launch_bounds__(256, 2) ffn2_hmma()
{
    extern __shared__ char sm[];
    const int combo = blockIdx.z;
    const int cnt = g_count[combo];
    const int bm = blockIdx.y * 128;
    if (bm >= cnt) return;
    const int e = combo & 7;
    const int b = combo >> 3;
    const int bn = blockIdx.x * 128;
    float c[2][8][4];
    hgemm_loop<Fdim>(g_ygf + (size_t)(combo * CAPMAX + bm) * Fdim,
                     g_w2f + ((size_t)e * Ddim + bn) * Fdim,
                     Fdim, Fdim, sm, c);
    const int lane = threadIdx.x & 31, wid = threadIdx.x >> 5;
    const int wm = (wid & 3) * 32, wn = (wid >> 2) * 64;
    const int col = bn + wn + (lane & 3) * 2;
#pragma unroll
    for (int i = 0; i < 2; i++) {
        const int m0 = bm + wm + i * 16 + (lane >> 2);
#pragma unroll
        for (int hh = 0; hh < 2; hh++) {
            const int m = m0 + hh * 8;
            if (m < cnt) {
                const int tok = g_etok[combo * CAPMAX + m];
                const float sc = g_escale[combo * CAPMAX + m];
                float* op = g_moe + ((size_t)(b * Sdim + tok)) * Ddim + col;
#pragma unroll
                for (int j = 0; j < 8; j++)
                    *(float2*)(op + j * 8) =
                        make_float2(sc * c[i][j][hh * 2], sc * c[i][j][hh * 2 + 1]);
            }
        }
    }
}

// ---------------- LN2 ----------------
__global__ void __launch_bounds__(128) add_ln_kernel(
    const float* __restrict__ a, const float* __restrict__ r,
    const float* __restrict__ g, const float* __restrict__ be,
    float* __restrict__ out)
{
    const int n = blockIdx.x;
    const int tid = threadIdx.x;
    __shared__ float red[4], red2[4];
    __shared__ float s_mu, s_rstd;
    const float* ap = a + (size_t)n * Ddim;
    const float* rp = r + (size_t)n * Ddim;
    float v[4];
    float sum = 0.0f, sq = 0.0f;
#pragma unroll
    for (int i = 0; i < 4; i++) {
        v[i] = ap[tid + i * 128] + rp[tid + i * 128];
        sum += v[i];
        sq = fmaf(v[i], v[i], sq);
    }
#pragma unroll
    for (int o = 16; o; o >>= 1) {
        sum += __shfl_xor_sync(0xffffffffu, sum, o);
        sq  += __shfl_xor_sync(0xffffffffu, sq, o);
    }
    if ((tid & 31) == 0) { red[tid >> 5] = sum; red2[tid >> 5] = sq; }
    __syncthreads();
    if (tid == 0) {
        float s = red[0] + red[1] + red[2] + red[3];
        float q = red2[0] + red2[1] + red2[2] + red2[3];
        float mu = s * (1.0f / 512.0f);
        s_mu = mu;
        s_rstd = rsqrtf(q * (1.0f / 512.0f) - mu * mu + 1e-5f);
    }
    __syncthreads();
    float mu = s_mu, rstd = s_rstd;
#pragma unroll
    for (int i = 0; i < 4; i++) {
        int d = tid + i * 128;
        out[(size_t)n * Ddim + d] = (v[i] - mu) * rstd * g[d] + be[d];
    }
}

// ---------------- launch ----------------
extern "C" void kernel_launch(void* const* d_in, const int* in_sizes, int n_in,
                              void* d_out, int out_size)
{
    const float* x     = (const float*)d_in[0];
    const float* in_w  = (const float*)d_in[1];
    const float* in_b  = (const float*)d_in[2];
    const float* out_w = (const float*)d_in[3];
    const float* out_b = (const float*)d_in[4];
    const float* ln1g  = (const float*)d_in[5];
    const float* ln1b  = (const float*)d_in[6];
    const float* ln2g  = (const float*)d_in[7];
    const float* ln2b  = (const float*)d_in[8];
    const float* rw    = (const float*)d_in[9];
    const float* wi    = (const float*)d_in[10];
    const float* wo    = (const float*)d_in[11];
    const int*   cap   = (const int*)d_in[12];

    float* out        = (float*)d_out;
    float* logits_out = out + (size_t)NTOK * Ddim;
    float* mask_out   = logits_out + (size_t)NTOK * Edim;

    float *p_aout, *p_h, *p_moe;
    cudaGetSymbolAddress((void**)&p_aout, g_aout);
    cudaGetSymbolAddress((void**)&p_h,    g_h);
    cudaGetSymbolAddress((void**)&p_moe,  g_moe);

    cudaFuncSetAttribute(qkv_hmma,     cudaFuncAttributeMaxDynamicSharedMemorySize, GEMM_SMEM);
    cudaFuncSetAttribute(outproj_hmma, cudaFuncAttributeMaxDynamicSharedMemorySize, GEMM_SMEM);
    cudaFuncSetAttribute(ffn1_hmma,    cudaFuncAttributeMaxDynamicSharedMemorySize, HGEMM_SMEM);
    cudaFuncSetAttribute(ffn2_hmma,    cudaFuncAttributeMaxDynamicSharedMemorySize, HGEMM_SMEM);
    cudaFuncSetAttribute(flash_attn_hmma, cudaFuncAttributeMaxDynamicSharedMemorySize, FA_SMEM);

    // 1) unified prep
    prep_kernel<<<19456, 256>>>(x, in_w, out_w, wi, wo);
    // 2) QKV projection
    qkv_hmma<<<dim3(QKVW / 128, NTOK / 128), 256, GEMM_SMEM>>>(in_b);
    // 3) V transpose+split
    v_trans_split_kernel<<<dim3(Sdim / 32, Ddim / 32, Bdim), 256>>>();
    // 4) flash attention (2 CTAs/SM floor)
    flash_attn_hmma<<<dim3(Sdim / 64, Hdim, Bdim), 128, FA_SMEM>>>();
    // 5) out-proj
    outproj_hmma<<<dim3(Ddim / 128, NTOK / 128), 256, GEMM_SMEM>>>(out_b);
    // 6) LN1 + router + moe zero + mask zero (fused)
    ln1_router_kernel<<<NTOK, 128>>>(p_aout, x, ln1g, ln1b, rw, p_h, logits_out, mask_out);
    // 7) capacity scan (warp-parallel prefix)
    capacity_kernel<<<Bdim, 256>>>(cap, mask_out);
    // 8) gather
    gather_kernel<<<(32 * CAPMAX) / 4, 256>>>();
    // 9) expert FFN
    ffn1_hmma<<<dim3(Fdim / 128, CAPMAX / 128, 32), 256, HGEMM_SMEM>>>();
    ffn2_hmma<<<dim3(Ddim / 128, CAPMAX / 128, 32), 256, HGEMM_SMEM>>>();
    // 10) LN2
    add_ln_kernel<<<NTOK, 128>>>(p_moe, p_h, ln2g, ln2b, out);
}